// round 11
// baseline (speedup 1.0000x reference)
#include <cuda_runtime.h>
#include <cuda_fp16.h>
#include <cstdint>

// ---------------------------------------------------------------------------
// SmallMLP_INR: fused 6-layer MLP, base-target ISA (compute_103-safe).
// fp16 m16n8k16 mma.sync + ldmatrix. CTA = 64 rows / 4 warps; warp = 64x64
// tile with a PRIVATE 4-slot cp.async ring of 32-K B chunks -> zero barriers
// in the mainloop. SMEM 107KB -> 2 decoupled CTAs per SM hide each other's
// stalls and epilogues.
// ---------------------------------------------------------------------------

#define THREADS 128
#define TILE_M  64
#define KDIM    256
#define NDIM    256

#define A_STRIDE 264       // halves; 528B rows -> ldmatrix conflict-free
#define SLOT_BYTES 4096    // 64 n-rows * 64B (32 k halves), swizzled
#define WARP_RING  16384   // 4 slots

// SMEM layout (bytes)
#define SM_W1    0        // 512 f32
#define SM_B1    2048
#define SM_B2    3072
#define SM_B3    4096
#define SM_B4    5120
#define SM_B5    6144
#define SM_W6    7168
#define SM_B6    8192
#define SM_PART  8208     // 4*64 f32 = 1024
#define SM_A     9232     // 64*264*2 = 33792
#define SM_RING  43136    // 128-aligned; 4 warps * 16384 = 65536
#define SMEM_TOTAL 108672

// Pre-transposed fp16 weights: g_WtH[l][n*256 + k] = (half)W_{l+2}[k][n]
__device__ __half g_WtH[4][KDIM * NDIM];

// ---------------------------------------------------------------------------
__device__ __forceinline__ uint32_t smem_u32(const void* p) {
    uint32_t a;
    asm("{ .reg .u64 t; cvta.to.shared.u64 t, %1; cvt.u32.u64 %0, t; }" : "=r"(a) : "l"(p));
    return a;
}

__device__ __forceinline__ void mma_f16(float* c, const uint32_t* a, const uint32_t* b) {
    asm volatile(
        "mma.sync.aligned.m16n8k16.row.col.f32.f16.f16.f32 "
        "{%0,%1,%2,%3}, {%4,%5,%6,%7}, {%8,%9}, {%0,%1,%2,%3};\n"
        : "+f"(c[0]), "+f"(c[1]), "+f"(c[2]), "+f"(c[3])
        : "r"(a[0]), "r"(a[1]), "r"(a[2]), "r"(a[3]), "r"(b[0]), "r"(b[1]));
}

#define LDMATRIX_X4(r0, r1, r2, r3, addr) \
    asm volatile("ldmatrix.sync.aligned.m8n8.x4.shared.b16 {%0,%1,%2,%3}, [%4];" \
                 : "=r"(r0), "=r"(r1), "=r"(r2), "=r"(r3) : "r"(addr))

__device__ __forceinline__ void cp_async16(uint32_t dst, const void* src) {
    asm volatile("cp.async.cg.shared.global [%0], [%1], 16;" :: "r"(dst), "l"(src) : "memory");
}
__device__ __forceinline__ void cp_commit() { asm volatile("cp.async.commit_group;" ::: "memory"); }
__device__ __forceinline__ void cp_wait3()  { asm volatile("cp.async.wait_group 3;" ::: "memory"); }
__device__ __forceinline__ void cp_wait2()  { asm volatile("cp.async.wait_group 2;" ::: "memory"); }
__device__ __forceinline__ void cp_wait1()  { asm volatile("cp.async.wait_group 1;" ::: "memory"); }
__device__ __forceinline__ void cp_wait0()  { asm volatile("cp.async.wait_group 0;" ::: "memory"); }

// Warp-private: load one 64n x 32k B chunk (4KB) into a ring slot.
// Rows are 64B (4 x 16B segments), swizzled: seg_phys = seg ^ ((row>>1)&3).
// Lane handles local rows lid and lid+32 (4 cp.async each).
__device__ __forceinline__ void load_wchunk(uint32_t slot, const __half* Wt,
                                            int ncol, int c, int lid) {
#pragma unroll
    for (int h = 0; h < 2; h++) {
        const int r = lid + h * 32;
        const uint32_t dst = slot + (uint32_t)r * 64;
        const uint32_t rsw = (uint32_t)((r >> 1) & 3);
        const __half* src = Wt + (size_t)(ncol + r) * KDIM + c * 32;
#pragma unroll
        for (uint32_t j = 0; j < 4; j++)
            cp_async16(dst + ((j ^ rsw) << 4), src + j * 8);
    }
    cp_commit();
}

// ---------------------------------------------------------------------------
// weight pre-transpose + fp16 round
// ---------------------------------------------------------------------------
__global__ void transpose_w_kernel(const float* __restrict__ W2, const float* __restrict__ W3,
                                   const float* __restrict__ W4, const float* __restrict__ W5) {
    __shared__ float t[32][33];
    const float* W = (blockIdx.z == 0) ? W2 : (blockIdx.z == 1) ? W3
                   : (blockIdx.z == 2) ? W4 : W5;
    const int nb = blockIdx.x * 32, kb = blockIdx.y * 32;
    const int tx = threadIdx.x, ty = threadIdx.y;
#pragma unroll
    for (int i = 0; i < 32; i += 8)
        t[ty + i][tx] = W[(size_t)(kb + ty + i) * 256 + (nb + tx)];
    __syncthreads();
    __half* dst = g_WtH[blockIdx.z];
#pragma unroll
    for (int i = 0; i < 32; i += 8)
        dst[(size_t)(nb + ty + i) * 256 + (kb + tx)] = __float2half_rn(t[tx][ty + i]);
}

// ---------------------------------------------------------------------------
// main fused kernel: CTA = 64 rows, warp = 64M x 64N, 2 CTAs/SM
// ---------------------------------------------------------------------------
__global__ void __launch_bounds__(THREADS, 2) mlp_kernel(
    const float* __restrict__ coords,
    const float* __restrict__ W1, const float* __restrict__ b1,
    const float* __restrict__ b2, const float* __restrict__ b3,
    const float* __restrict__ b4, const float* __restrict__ b5,
    const float* __restrict__ W6, const float* __restrict__ b6,
    float* __restrict__ out) {
    extern __shared__ __align__(128) char smem[];
    const uint32_t sb = smem_u32(smem);
    const int tid = threadIdx.x;
    const int wid = tid >> 5;
    const int lid = tid & 31;
    const int g = lid >> 2;
    const int t = lid & 3;
    const int ncol = wid * 64;           // this warp's private 64-col N slice
    const int row_base = blockIdx.x * TILE_M;

    float* sW1 = (float*)(smem + SM_W1);
    float* sB1 = (float*)(smem + SM_B1);
    float* sB2 = (float*)(smem + SM_B2);
    float* sB3 = (float*)(smem + SM_B3);
    float* sB4 = (float*)(smem + SM_B4);
    float* sB5 = (float*)(smem + SM_B5);
    float* sW6 = (float*)(smem + SM_W6);
    float* sB6 = (float*)(smem + SM_B6);
    float* sPart = (float*)(smem + SM_PART);
    __half* sA = (__half*)(smem + SM_A);
    const uint32_t ring = sb + SM_RING + (uint32_t)wid * WARP_RING;

    // stage small params (128 threads)
    sW1[tid]       = W1[tid];
    sW1[tid + 128] = W1[tid + 128];
    sW1[tid + 256] = W1[tid + 256];
    sW1[tid + 384] = W1[tid + 384];
    sB1[tid] = b1[tid];   sB1[tid + 128] = b1[tid + 128];
    sB2[tid] = b2[tid];   sB2[tid + 128] = b2[tid + 128];
    sB3[tid] = b3[tid];   sB3[tid + 128] = b3[tid + 128];
    sB4[tid] = b4[tid];   sB4[tid + 128] = b4[tid + 128];
    sB5[tid] = b5[tid];   sB5[tid + 128] = b5[tid + 128];
    sW6[tid] = W6[tid];   sW6[tid + 128] = W6[tid + 128];
    if (tid == 0) sB6[0] = b6[0];

    // prologue: warp prefetches its chunks 0..2 of layer 2 (slots 0..2)
    load_wchunk(ring,                  g_WtH[0], ncol, 0, lid);
    load_wchunk(ring + SLOT_BYTES,     g_WtH[0], ncol, 1, lid);
    load_wchunk(ring + 2 * SLOT_BYTES, g_WtH[0], ncol, 2, lid);

    __syncthreads();

    // ---- Layer 1 (fan-in 2, FFMA) -> sA (fp16) ----
    {
        const int row = tid >> 1;
        const int j0  = (tid & 1) * 128;
        const float2 c = *(const float2*)(coords + 2 * (size_t)(row_base + row));
        __half* dst = sA + (size_t)row * A_STRIDE;
#pragma unroll
        for (int j = 0; j < 128; j += 2) {
            const int jj = j0 + j;
            float v0 = fmaxf(fmaf(c.x, sW1[jj + 0], fmaf(c.y, sW1[256 + jj + 0], sB1[jj + 0])), 0.f);
            float v1 = fmaxf(fmaf(c.x, sW1[jj + 1], fmaf(c.y, sW1[256 + jj + 1], sB1[jj + 1])), 0.f);
            *(__half2*)(dst + jj) = __floats2half2_rn(v0, v1);
        }
    }
    __syncthreads();   // sA ready for all warps

    // ldmatrix lane-address bases
    // A: lanes 0-7 rows 0..7 @k | 8-15 rows 8..15 @k | 16-23 rows 0..7 @k+8 | 24-31 rows 8..15 @k+8
    const uint32_t aA = sb + SM_A +
        (uint32_t)(((lid & 15) * A_STRIDE + ((lid & 16) ? 8 : 0)) * 2);
    // B (swizzled 64B rows): local row = base_row + jp*16,
    // base_row = (lid&7)+((lid&16)?8:0); seg = 2*ks + b8; phys = seg ^ rsw
    const int brow = (lid & 7) + ((lid & 16) ? 8 : 0);
    const uint32_t bRow = (uint32_t)brow * 64;
    const uint32_t rsw = (uint32_t)((brow >> 1) & 3);
    const uint32_t b8 = (uint32_t)((lid >> 3) & 1);

    // ---- Layers 2..5: per-warp flat 32-chunk pipeline (32-K chunks) ----
#pragma unroll 1
    for (int l = 0; l < 4; l++) {
        float acc[4][8][4];
#pragma unroll
        for (int i = 0; i < 4; i++)
#pragma unroll
            for (int j = 0; j < 8; j++)
#pragma unroll
                for (int c = 0; c < 4; c++) acc[i][j][c] = 0.f;

#pragma unroll
        for (int c = 0; c < 8; c++) {
            const int f = l * 8 + c;          // flat chunk index, slot = f&3

            // prefetch chunk f+3 into slot (f+3)&3 (this warp finished reading
            // chunk f-1 last iteration; warp-private -> no barrier needed)
            if (f + 3 < 32) {
                const int q = f + 3;
                load_wchunk(ring + (uint32_t)(q & 3) * SLOT_BYTES,
                            g_WtH[q >> 3], ncol, q & 7, lid);
            }

            // wait for chunk f (pending = f+1..f+3 at steady state)
            if (l == 3) {
                if (c < 5)       cp_wait3();
                else if (c == 5) cp_wait2();
                else if (c == 6) cp_wait1();
                else             cp_wait0();
            } else {
                cp_wait3();
            }

            const uint32_t slot = ring + (uint32_t)(f & 3) * SLOT_BYTES;
#pragma unroll
            for (int ks = 0; ks < 2; ks++) {
                const int k0 = c * 32 + ks * 16;   // k offset in sA (halves)
                const uint32_t soff = ((((uint32_t)(2 * ks) + b8) ^ rsw) << 4);
                uint32_t b[4][4];
#pragma unroll
                for (int jp = 0; jp < 4; jp++)
                    LDMATRIX_X4(b[jp][0], b[jp][1], b[jp][2], b[jp][3],
                                slot + bRow + (uint32_t)jp * (16 * 64) + soff);
#pragma unroll
                for (int i = 0; i < 4; i++) {
                    uint32_t a[4];
                    LDMATRIX_X4(a[0], a[1], a[2], a[3],
                                aA + (uint32_t)(i * 16 * A_STRIDE + k0) * 2);
#pragma unroll
                    for (int j = 0; j < 8; j++)
                        mma_f16(acc[i][j], a, &b[j >> 1][(j & 1) * 2]);
                }
            }
        }

        __syncthreads();   // all warps done reading sA this layer

        if (l < 3) {
            // epilogue: sA <- (half)relu(D + bias) for this warp's 64 cols
            const float* bias = (l == 0) ? sB2 : (l == 1) ? sB3 : sB4;
#pragma unroll
            for (int j = 0; j < 8; j++) {
                const int col = ncol + 8 * j + 2 * t;
                const float bs0 = bias[col], bs1 = bias[col + 1];
#pragma unroll
                for (int i = 0; i < 4; i++) {
                    const int row = 16 * i + g;
                    *(__half2*)(sA + (size_t)row * A_STRIDE + col) =
                        __floats2half2_rn(fmaxf(acc[i][j][0] + bs0, 0.f),
                                          fmaxf(acc[i][j][1] + bs1, 0.f));
                    *(__half2*)(sA + (size_t)(row + 8) * A_STRIDE + col) =
                        __floats2half2_rn(fmaxf(acc[i][j][2] + bs0, 0.f),
                                          fmaxf(acc[i][j][3] + bs1, 0.f));
                }
            }
            __syncthreads();   // epilogue visible before next layer reads
        } else {
            // ---- Layer 6: out = relu(D + b5) . W6 + b6 ----
            float r0[4] = {0.f, 0.f, 0.f, 0.f};
            float r1[4] = {0.f, 0.f, 0.f, 0.f};
#pragma unroll
            for (int j = 0; j < 8; j++) {
                const int col = ncol + 8 * j + 2 * t;
                const float w0 = sW6[col], w1 = sW6[col + 1];
                const float s0 = sB5[col], s1 = sB5[col + 1];
#pragma unroll
                for (int i = 0; i < 4; i++) {
                    r0[i] = fmaf(fmaxf(acc[i][j][0] + s0, 0.f), w0, r0[i]);
                    r0[i] = fmaf(fmaxf(acc[i][j][1] + s1, 0.f), w1, r0[i]);
                    r1[i] = fmaf(fmaxf(acc[i][j][2] + s0, 0.f), w0, r1[i]);
                    r1[i] = fmaf(fmaxf(acc[i][j][3] + s1, 0.f), w1, r1[i]);
                }
            }
#pragma unroll
            for (int d = 1; d <= 2; d <<= 1) {
#pragma unroll
                for (int i = 0; i < 4; i++) {
                    r0[i] += __shfl_xor_sync(0xFFFFFFFFu, r0[i], d);
                    r1[i] += __shfl_xor_sync(0xFFFFFFFFu, r1[i], d);
                }
            }
            if (t == 0) {
                float* part = sPart + wid * 64;
#pragma unroll
                for (int i = 0; i < 4; i++) {
                    part[16 * i + g]     = r0[i];
                    part[16 * i + g + 8] = r1[i];
                }
            }
            __syncthreads();
            if (tid < TILE_M)
                out[row_base + tid] = sPart[tid] + sPart[64 + tid] +
                                      sPart[128 + tid] + sPart[192 + tid] + sB6[0];
        }
    }
}

// ---------------------------------------------------------------------------
extern "C" void kernel_launch(void* const* d_in, const int* in_sizes, int n_in,
                              void* d_out, int out_size) {
    const float* coords = (const float*)d_in[0];
    const float* W1 = (const float*)d_in[1];
    const float* b1 = (const float*)d_in[2];
    const float* W2 = (const float*)d_in[3];
    const float* b2 = (const float*)d_in[4];
    const float* W3 = (const float*)d_in[5];
    const float* b3 = (const float*)d_in[6];
    const float* W4 = (const float*)d_in[7];
    const float* b4 = (const float*)d_in[8];
    const float* W5 = (const float*)d_in[9];
    const float* b5 = (const float*)d_in[10];
    const float* W6 = (const float*)d_in[11];
    const float* b6 = (const float*)d_in[12];
    float* out = (float*)d_out;

    const int n = in_sizes[0] / 2;  // rows

    transpose_w_kernel<<<dim3(NDIM / 32, KDIM / 32, 4), dim3(32, 8)>>>(W2, W3, W4, W5);

    cudaFuncSetAttribute(mlp_kernel, cudaFuncAttributeMaxDynamicSharedMemorySize, SMEM_TOTAL);
    mlp_kernel<<<n / TILE_M, THREADS, SMEM_TOTAL>>>(coords, W1, b1, b2, b3, b4, b5,
                                                    W6, b6, out);
}

// round 12
// speedup vs baseline: 1.0427x; 1.0427x over previous
#include <cuda_runtime.h>
#include <cuda_fp16.h>
#include <cstdint>

// ---------------------------------------------------------------------------
// SmallMLP_INR: fused 6-layer MLP, base-target ISA (compute_103-safe).
// fp16 m16n8k16 mma.sync + ldmatrix. Single 128-row CTA, 512 threads:
// 16 warps of 32M x 64N tiles (4 warps per SMSP) to cover HMMA issue/latency
// gaps. Flat 16-chunk cp.async ring (4 slots, depth 3), 1 barrier per chunk.
// ---------------------------------------------------------------------------

#define THREADS 512
#define TILE_M  128
#define KDIM    256
#define NDIM    256

#define A_STRIDE 264       // halves; 528B rows -> ldmatrix conflict-free
#define B_STRIDE 72        // halves; 144B rows -> ldmatrix conflict-free
#define SLOT_BYTES 36864   // 256 * 72 * 2

// SMEM layout (bytes)
#define SM_W1    0        // 512 f32
#define SM_B1    2048
#define SM_B2    3072
#define SM_B3    4096
#define SM_B4    5120
#define SM_B5    6144
#define SM_W6    7168
#define SM_B6    8192
#define SM_PART  8208     // 4*128 f32 = 2048
#define SM_A     10496    // 128*264*2 = 67584
#define SM_RING  78080    // 4 * 36864 = 147456
#define SMEM_TOTAL 225536

// Pre-transposed fp16 weights: g_WtH[l][n*256 + k] = (half)W_{l+2}[k][n]
__device__ __half g_WtH[4][KDIM * NDIM];

// ---------------------------------------------------------------------------
__device__ __forceinline__ uint32_t smem_u32(const void* p) {
    uint32_t a;
    asm("{ .reg .u64 t; cvta.to.shared.u64 t, %1; cvt.u32.u64 %0, t; }" : "=r"(a) : "l"(p));
    return a;
}

__device__ __forceinline__ void mma_f16(float* c, const uint32_t* a, const uint32_t* b) {
    asm volatile(
        "mma.sync.aligned.m16n8k16.row.col.f32.f16.f16.f32 "
        "{%0,%1,%2,%3}, {%4,%5,%6,%7}, {%8,%9}, {%0,%1,%2,%3};\n"
        : "+f"(c[0]), "+f"(c[1]), "+f"(c[2]), "+f"(c[3])
        : "r"(a[0]), "r"(a[1]), "r"(a[2]), "r"(a[3]), "r"(b[0]), "r"(b[1]));
}

#define LDMATRIX_X4(r0, r1, r2, r3, addr) \
    asm volatile("ldmatrix.sync.aligned.m8n8.x4.shared.b16 {%0,%1,%2,%3}, [%4];" \
                 : "=r"(r0), "=r"(r1), "=r"(r2), "=r"(r3) : "r"(addr))

__device__ __forceinline__ void cp_async16(uint32_t dst, const void* src) {
    asm volatile("cp.async.cg.shared.global [%0], [%1], 16;" :: "r"(dst), "l"(src) : "memory");
}
__device__ __forceinline__ void cp_commit() { asm volatile("cp.async.commit_group;" ::: "memory"); }
__device__ __forceinline__ void cp_wait2()  { asm volatile("cp.async.wait_group 2;" ::: "memory"); }
__device__ __forceinline__ void cp_wait1()  { asm volatile("cp.async.wait_group 1;" ::: "memory"); }
__device__ __forceinline__ void cp_wait0()  { asm volatile("cp.async.wait_group 0;" ::: "memory"); }

// CTA-wide (512 thr): one 256x64 weight chunk (32KB) into a ring slot.
// Thread pair handles one n-row: each loads 32 halves = 4 x 16B cp.async.
__device__ __forceinline__ void load_chunk(uint32_t slot, const __half* Wt,
                                           int c, int tid) {
    const int row = tid >> 1;
    const int ko  = (tid & 1) * 32;
    uint32_t dst = slot + (uint32_t)row * (B_STRIDE * 2) + (uint32_t)ko * 2;
    const __half* src = Wt + (size_t)row * KDIM + c * 64 + ko;
#pragma unroll
    for (int j = 0; j < 4; j++)
        cp_async16(dst + j * 16, src + j * 8);
    cp_commit();
}

// ---------------------------------------------------------------------------
// weight pre-transpose + fp16 round
// ---------------------------------------------------------------------------
__global__ void transpose_w_kernel(const float* __restrict__ W2, const float* __restrict__ W3,
                                   const float* __restrict__ W4, const float* __restrict__ W5) {
    __shared__ float t[32][33];
    const float* W = (blockIdx.z == 0) ? W2 : (blockIdx.z == 1) ? W3
                   : (blockIdx.z == 2) ? W4 : W5;
    const int nb = blockIdx.x * 32, kb = blockIdx.y * 32;
    const int tx = threadIdx.x, ty = threadIdx.y;
#pragma unroll
    for (int i = 0; i < 32; i += 8)
        t[ty + i][tx] = W[(size_t)(kb + ty + i) * 256 + (nb + tx)];
    __syncthreads();
    __half* dst = g_WtH[blockIdx.z];
#pragma unroll
    for (int i = 0; i < 32; i += 8)
        dst[(size_t)(nb + ty + i) * 256 + (kb + tx)] = __float2half_rn(t[tx][ty + i]);
}

// ---------------------------------------------------------------------------
// main fused kernel: one CTA = 128 rows; 16 warps of 32M x 64N tiles
// ---------------------------------------------------------------------------
__global__ void __launch_bounds__(THREADS, 1) mlp_kernel(
    const float* __restrict__ coords,
    const float* __restrict__ W1, const float* __restrict__ b1,
    const float* __restrict__ b2, const float* __restrict__ b3,
    const float* __restrict__ b4, const float* __restrict__ b5,
    const float* __restrict__ W6, const float* __restrict__ b6,
    float* __restrict__ out) {
    extern __shared__ __align__(128) char smem[];
    const uint32_t sb = smem_u32(smem);
    const int tid = threadIdx.x;
    const int wid = tid >> 5;
    const int lid = tid & 31;
    const int g = lid >> 2;
    const int t = lid & 3;
    const int mrow = (wid & 3) * 32;      // 4 M-slots of 32 rows
    const int ncol = (wid >> 2) * 64;     // 4 N-slots of 64 cols
    const int row_base = blockIdx.x * TILE_M;

    float* sW1 = (float*)(smem + SM_W1);
    float* sB1 = (float*)(smem + SM_B1);
    float* sB2 = (float*)(smem + SM_B2);
    float* sB3 = (float*)(smem + SM_B3);
    float* sB4 = (float*)(smem + SM_B4);
    float* sB5 = (float*)(smem + SM_B5);
    float* sW6 = (float*)(smem + SM_W6);
    float* sB6 = (float*)(smem + SM_B6);
    float* sPart = (float*)(smem + SM_PART);
    __half* sA = (__half*)(smem + SM_A);
    const uint32_t rb = sb + SM_RING;

    // stage small params
    if (tid < 256) {
        sW1[tid]       = W1[tid];
        sW1[tid + 256] = W1[tid + 256];
        sB1[tid] = b1[tid];
        sB2[tid] = b2[tid];
        sB3[tid] = b3[tid];
        sB4[tid] = b4[tid];
        sB5[tid] = b5[tid];
        sW6[tid] = W6[tid];
    }
    if (tid == 0) sB6[0] = b6[0];

    // prologue: prefetch chunks 0..2 of layer 2 (slots 0..2)
    load_chunk(rb,                  g_WtH[0], 0, tid);
    load_chunk(rb + SLOT_BYTES,     g_WtH[0], 1, tid);
    load_chunk(rb + 2 * SLOT_BYTES, g_WtH[0], 2, tid);

    __syncthreads();

    // ---- Layer 1 (fan-in 2, FFMA) -> sA (fp16) ----
    {
        const int row = tid >> 2;
        const int j0  = (tid & 3) * 64;
        const float2 c = *(const float2*)(coords + 2 * (size_t)(row_base + row));
        __half* dst = sA + (size_t)row * A_STRIDE;
#pragma unroll
        for (int j = 0; j < 64; j += 2) {
            const int jj = j0 + j;
            float v0 = fmaxf(fmaf(c.x, sW1[jj + 0], fmaf(c.y, sW1[256 + jj + 0], sB1[jj + 0])), 0.f);
            float v1 = fmaxf(fmaf(c.x, sW1[jj + 1], fmaf(c.y, sW1[256 + jj + 1], sB1[jj + 1])), 0.f);
            *(__half2*)(dst + jj) = __floats2half2_rn(v0, v1);
        }
    }

    // ldmatrix lane-address bases
    const uint32_t aA = sb + SM_A +
        (uint32_t)(((mrow + (lid & 15)) * A_STRIDE + ((lid & 16) ? 8 : 0)) * 2);
    const uint32_t bOff =
        (uint32_t)((ncol + (lid & 7) + ((lid & 16) ? 8 : 0)) * B_STRIDE * 2 +
                   ((lid & 8) ? 16 : 0));

    // ---- Layers 2..5: flat 16-chunk pipeline, slot index == c ----
#pragma unroll 1
    for (int l = 0; l < 4; l++) {
        float acc[2][8][4];
#pragma unroll
        for (int i = 0; i < 2; i++)
#pragma unroll
            for (int j = 0; j < 8; j++)
#pragma unroll
                for (int c = 0; c < 4; c++) acc[i][j][c] = 0.f;

#pragma unroll
        for (int c = 0; c < 4; c++) {
            if (l == 3 && c == 2)      cp_wait1();
            else if (l == 3 && c == 3) cp_wait0();
            else                       cp_wait2();
            __syncthreads();

            const uint32_t bB = rb + (uint32_t)c * SLOT_BYTES + bOff;
#pragma unroll
            for (int ks = 0; ks < 4; ks++) {
                const int k0 = c * 64 + ks * 16;   // global k (halves)
                uint32_t b[4][4];
#pragma unroll
                for (int jp = 0; jp < 4; jp++) {
                    const uint32_t addr = bB + (uint32_t)(jp * 16 * B_STRIDE + ks * 16) * 2;
                    LDMATRIX_X4(b[jp][0], b[jp][1], b[jp][2], b[jp][3], addr);
                }
#pragma unroll
                for (int i = 0; i < 2; i++) {
                    uint32_t a[4];
                    const uint32_t addr = aA + (uint32_t)(i * 16 * A_STRIDE + k0) * 2;
                    LDMATRIX_X4(a[0], a[1], a[2], a[3], addr);
#pragma unroll
                    for (int j = 0; j < 8; j++)
                        mma_f16(acc[i][j], a, &b[j >> 1][(j & 1) * 2]);
                }
            }

            // prefetch chunk f+3 into slot (c+3)&3 (freed by chunk f-1)
            const int q = l * 4 + c + 3;
            if (q < 16)
                load_chunk(rb + (uint32_t)(q & 3) * SLOT_BYTES, g_WtH[q >> 2],
                           q & 3, tid);
        }

        __syncthreads();   // all warps done reading sA

        if (l < 3) {
            // epilogue: sA <- (half)relu(D + bias) for this warp's 32x64 tile
            const float* bias = (l == 0) ? sB2 : (l == 1) ? sB3 : sB4;
#pragma unroll
            for (int j = 0; j < 8; j++) {
                const int col = ncol + 8 * j + 2 * t;
                const float bs0 = bias[col], bs1 = bias[col + 1];
#pragma unroll
                for (int i = 0; i < 2; i++) {
                    const int row = mrow + 16 * i + g;
                    *(__half2*)(sA + (size_t)row * A_STRIDE + col) =
                        __floats2half2_rn(fmaxf(acc[i][j][0] + bs0, 0.f),
                                          fmaxf(acc[i][j][1] + bs1, 0.f));
                    *(__half2*)(sA + (size_t)(row + 8) * A_STRIDE + col) =
                        __floats2half2_rn(fmaxf(acc[i][j][2] + bs0, 0.f),
                                          fmaxf(acc[i][j][3] + bs1, 0.f));
                }
            }
            // next chunk's __syncthreads orders these writes before reads
        } else {
            // ---- Layer 6: out = relu(D + b5) . W6 + b6 ----
            float r0[2] = {0.f, 0.f};
            float r1[2] = {0.f, 0.f};
#pragma unroll
            for (int j = 0; j < 8; j++) {
                const int col = ncol + 8 * j + 2 * t;
                const float w0 = sW6[col], w1 = sW6[col + 1];
                const float s0 = sB5[col], s1 = sB5[col + 1];
#pragma unroll
                for (int i = 0; i < 2; i++) {
                    r0[i] = fmaf(fmaxf(acc[i][j][0] + s0, 0.f), w0, r0[i]);
                    r0[i] = fmaf(fmaxf(acc[i][j][1] + s1, 0.f), w1, r0[i]);
                    r1[i] = fmaf(fmaxf(acc[i][j][2] + s0, 0.f), w0, r1[i]);
                    r1[i] = fmaf(fmaxf(acc[i][j][3] + s1, 0.f), w1, r1[i]);
                }
            }
#pragma unroll
            for (int d = 1; d <= 2; d <<= 1) {
#pragma unroll
                for (int i = 0; i < 2; i++) {
                    r0[i] += __shfl_xor_sync(0xFFFFFFFFu, r0[i], d);
                    r1[i] += __shfl_xor_sync(0xFFFFFFFFu, r1[i], d);
                }
            }
            if (t == 0) {
                float* part = sPart + (wid >> 2) * 128;
#pragma unroll
                for (int i = 0; i < 2; i++) {
                    part[mrow + 16 * i + g]     = r0[i];
                    part[mrow + 16 * i + g + 8] = r1[i];
                }
            }
            __syncthreads();
            if (tid < TILE_M)
                out[row_base + tid] = sPart[tid] + sPart[128 + tid] +
                                      sPart[256 + tid] + sPart[384 + tid] + sB6[0];
        }
    }
}

// ---------------------------------------------------------------------------
extern "C" void kernel_launch(void* const* d_in, const int* in_sizes, int n_in,
                              void* d_out, int out_size) {
    const float* coords = (const float*)d_in[0];
    const float* W1 = (const float*)d_in[1];
    const float* b1 = (const float*)d_in[2];
    const float* W2 = (const float*)d_in[3];
    const float* b2 = (const float*)d_in[4];
    const float* W3 = (const float*)d_in[5];
    const float* b3 = (const float*)d_in[6];
    const float* W4 = (const float*)d_in[7];
    const float* b4 = (const float*)d_in[8];
    const float* W5 = (const float*)d_in[9];
    const float* b5 = (const float*)d_in[10];
    const float* W6 = (const float*)d_in[11];
    const float* b6 = (const float*)d_in[12];
    float* out = (float*)d_out;

    const int n = in_sizes[0] / 2;  // rows

    transpose_w_kernel<<<dim3(NDIM / 32, KDIM / 32, 4), dim3(32, 8)>>>(W2, W3, W4, W5);

    cudaFuncSetAttribute(mlp_kernel, cudaFuncAttributeMaxDynamicSharedMemorySize, SMEM_TOTAL);
    mlp_kernel<<<n / TILE_M, THREADS, SMEM_TOTAL>>>(coords, W1, b1, b2, b3, b4, b5,
                                                    W6, b6, out);
}

// round 13
// speedup vs baseline: 1.2085x; 1.1591x over previous
#include <cuda_runtime.h>
#include <cuda_fp16.h>
#include <cstdint>

// ---------------------------------------------------------------------------
// SmallMLP_INR: fused 6-layer MLP, base-target ISA (compute_103-safe).
// fp16 m16n8k16 mma.sync + ldmatrix (legacy tensor path; tcgen05 rejected by
// the harness's compute_103 PTX target). R4 structure — warp-private B
// pipelines, zero mainloop CTA barriers — made PERSISTENT: #SM CTAs
// grid-stride over tiles and the cp.async chunk stream runs continuously
// across tiles, eliminating wave transitions and tail idle.
// ---------------------------------------------------------------------------

#define THREADS 256
#define TILE_M  128
#define KDIM    256
#define NDIM    256
#define CHUNK   64

#define A_STRIDE 264   // halves; 528B rows -> ldmatrix conflict-free
#define B_STRIDE 264

// SMEM layout (bytes)
#define SM_W1    0        // 512 f32
#define SM_B1    2048
#define SM_B2    3072
#define SM_B3    4096
#define SM_B4    5120
#define SM_B5    6144
#define SM_W6    7168
#define SM_B6    8192
#define SM_PART  8208     // 8*128 f32 = 4096
#define SM_A     12416    // 128*264*2 = 67584
#define SM_B     80000    // 256*264*2 = 135168
#define SMEM_TOTAL 215168

// Pre-transposed fp16 weights: g_WtH[l][n*256 + k] = (half)W_{l+2}[k][n]
__device__ __half g_WtH[4][KDIM * NDIM];

// ---------------------------------------------------------------------------
__device__ __forceinline__ uint32_t smem_u32(const void* p) {
    uint32_t a;
    asm("{ .reg .u64 t; cvta.to.shared.u64 t, %1; cvt.u32.u64 %0, t; }" : "=r"(a) : "l"(p));
    return a;
}

__device__ __forceinline__ void mma_f16(float* c, const uint32_t* a, const uint32_t* b) {
    asm volatile(
        "mma.sync.aligned.m16n8k16.row.col.f32.f16.f16.f32 "
        "{%0,%1,%2,%3}, {%4,%5,%6,%7}, {%8,%9}, {%0,%1,%2,%3};\n"
        : "+f"(c[0]), "+f"(c[1]), "+f"(c[2]), "+f"(c[3])
        : "r"(a[0]), "r"(a[1]), "r"(a[2]), "r"(a[3]), "r"(b[0]), "r"(b[1]));
}

#define LDMATRIX_X4(r0, r1, r2, r3, addr) \
    asm volatile("ldmatrix.sync.aligned.m8n8.x4.shared.b16 {%0,%1,%2,%3}, [%4];" \
                 : "=r"(r0), "=r"(r1), "=r"(r2), "=r"(r3) : "r"(addr))

__device__ __forceinline__ void cp_async16(uint32_t dst, const void* src) {
    asm volatile("cp.async.cg.shared.global [%0], [%1], 16;" :: "r"(dst), "l"(src) : "memory");
}
__device__ __forceinline__ void cp_commit() { asm volatile("cp.async.commit_group;" ::: "memory"); }
__device__ __forceinline__ void cp_wait(int n) {
    if (n == 0)      asm volatile("cp.async.wait_group 0;" ::: "memory");
    else if (n == 1) asm volatile("cp.async.wait_group 1;" ::: "memory");
    else if (n == 2) asm volatile("cp.async.wait_group 2;" ::: "memory");
    else             asm volatile("cp.async.wait_group 3;" ::: "memory");
}

// Warp-private: load chunk c (k in [64c,64c+64)) of this warp's 32-row B slice.
__device__ __forceinline__ void load_wchunk(uint32_t sbB, const __half* Wt,
                                            int nbase, int c, int lane) {
    const int row = nbase + lane;
    uint32_t dst = sbB + (uint32_t)(row * B_STRIDE + c * 64) * 2;
    const __half* src = Wt + (size_t)row * KDIM + c * 64;
#pragma unroll
    for (int j = 0; j < 8; j++)
        cp_async16(dst + j * 16, src + j * 8);
    cp_commit();
}

// ---------------------------------------------------------------------------
// weight pre-transpose + fp16 round
// ---------------------------------------------------------------------------
__global__ void transpose_w_kernel(const float* __restrict__ W2, const float* __restrict__ W3,
                                   const float* __restrict__ W4, const float* __restrict__ W5) {
    __shared__ float t[32][33];
    const float* W = (blockIdx.z == 0) ? W2 : (blockIdx.z == 1) ? W3
                   : (blockIdx.z == 2) ? W4 : W5;
    const int nb = blockIdx.x * 32, kb = blockIdx.y * 32;
    const int tx = threadIdx.x, ty = threadIdx.y;
#pragma unroll
    for (int i = 0; i < 32; i += 8)
        t[ty + i][tx] = W[(size_t)(kb + ty + i) * 256 + (nb + tx)];
    __syncthreads();
    __half* dst = g_WtH[blockIdx.z];
#pragma unroll
    for (int i = 0; i < 32; i += 8)
        dst[(size_t)(nb + ty + i) * 256 + (kb + tx)] = __float2half_rn(t[tx][ty + i]);
}

// ---------------------------------------------------------------------------
// main persistent kernel: CTA grid-strides over 128-row tiles;
// warp = 128M x 32N; B chunk stream continuous across tiles
// ---------------------------------------------------------------------------
__global__ void __launch_bounds__(THREADS, 1) mlp_kernel(
    const float* __restrict__ coords,
    const float* __restrict__ W1, const float* __restrict__ b1,
    const float* __restrict__ b2, const float* __restrict__ b3,
    const float* __restrict__ b4, const float* __restrict__ b5,
    const float* __restrict__ W6, const float* __restrict__ b6,
    float* __restrict__ out, int ntiles) {
    extern __shared__ __align__(128) char smem[];
    const uint32_t sb = smem_u32(smem);
    const int tid = threadIdx.x;
    const int wid = tid >> 5;
    const int lid = tid & 31;
    const int g = lid >> 2;
    const int t = lid & 3;
    const int nbase = wid * 32;      // this warp's private N slice

    float* sW1 = (float*)(smem + SM_W1);
    float* sB1 = (float*)(smem + SM_B1);
    float* sB2 = (float*)(smem + SM_B2);
    float* sB3 = (float*)(smem + SM_B3);
    float* sB4 = (float*)(smem + SM_B4);
    float* sB5 = (float*)(smem + SM_B5);
    float* sW6 = (float*)(smem + SM_W6);
    float* sB6 = (float*)(smem + SM_B6);
    float* sPart = (float*)(smem + SM_PART);
    __half* sA = (__half*)(smem + SM_A);

    // stage small params
    sW1[tid]       = W1[tid];
    sW1[tid + 256] = W1[tid + 256];
    sB1[tid] = b1[tid];
    sB2[tid] = b2[tid];
    sB3[tid] = b3[tid];
    sB4[tid] = b4[tid];
    sB5[tid] = b5[tid];
    sW6[tid] = W6[tid];
    if (tid == 0) sB6[0] = b6[0];

    // prologue: each warp streams layer-2 B slice (4 chunk-groups)
    load_wchunk(sb + SM_B, g_WtH[0], nbase, 0, lid);
    load_wchunk(sb + SM_B, g_WtH[0], nbase, 1, lid);
    load_wchunk(sb + SM_B, g_WtH[0], nbase, 2, lid);
    load_wchunk(sb + SM_B, g_WtH[0], nbase, 3, lid);

    __syncthreads();

    // ldmatrix lane-address bases
    const uint32_t aA = sb + SM_A +
        (uint32_t)(((lid & 15) * A_STRIDE + ((lid & 16) ? 8 : 0)) * 2);
    const uint32_t bB = sb + SM_B +
        (uint32_t)((nbase + (lid & 7) + ((lid & 16) ? 8 : 0)) * B_STRIDE * 2 +
                   ((lid & 8) ? 16 : 0));

    const int stride = gridDim.x;

#pragma unroll 1
    for (int tile = blockIdx.x; tile < ntiles; tile += stride) {
        const bool lastT = (tile + stride >= ntiles);
        const int row_base = tile * TILE_M;

        // ---- Layer 1 (fan-in 2, FFMA) -> sA (fp16) ----
        {
            const int row = tid >> 1;
            const int j0  = (tid & 1) * 128;
            const float2 c = *(const float2*)(coords + 2 * (size_t)(row_base + row));
            __half* dst = sA + (size_t)row * A_STRIDE;
#pragma unroll
            for (int j = 0; j < 128; j += 2) {
                const int jj = j0 + j;
                float v0 = fmaxf(fmaf(c.x, sW1[jj + 0], fmaf(c.y, sW1[256 + jj + 0], sB1[jj + 0])), 0.f);
                float v1 = fmaxf(fmaf(c.x, sW1[jj + 1], fmaf(c.y, sW1[256 + jj + 1], sB1[jj + 1])), 0.f);
                *(__half2*)(dst + jj) = __floats2half2_rn(v0, v1);
            }
        }
        __syncthreads();

        // ---- Layers 2..5 ----
#pragma unroll 1
        for (int l = 0; l < 4; l++) {
            float acc[8][4][4];
#pragma unroll
            for (int i = 0; i < 8; i++)
#pragma unroll
                for (int j = 0; j < 4; j++)
#pragma unroll
                    for (int c = 0; c < 4; c++) acc[i][j][c] = 0.f;

            const bool drain = lastT && (l == 3);
#pragma unroll
            for (int c = 0; c < 4; c++) {
                if (drain) cp_wait(3 - c); else cp_wait(3);
                __syncwarp();

#pragma unroll
                for (int ks = 0; ks < 4; ks++) {
                    const int k0 = c * 64 + ks * 16;
                    uint32_t b[2][4];
#pragma unroll
                    for (int np = 0; np < 2; np++) {
                        const uint32_t addr = bB + (uint32_t)(np * 16 * B_STRIDE + k0) * 2;
                        LDMATRIX_X4(b[np][0], b[np][1], b[np][2], b[np][3], addr);
                    }
#pragma unroll
                    for (int i = 0; i < 8; i++) {
                        uint32_t a[4];
                        const uint32_t addr = aA + (uint32_t)(i * 16 * A_STRIDE + k0) * 2;
                        LDMATRIX_X4(a[0], a[1], a[2], a[3], addr);
#pragma unroll
                        for (int j = 0; j < 4; j++)
                            mma_f16(acc[i][j], a, &b[j >> 1][(j & 1) * 2]);
                    }
                }

                // prefetch same chunk of next layer (next tile's layer 2 when
                // l==3) into the slot just consumed — stream never drains
                // except on the CTA's very last tile
                if (!drain)
                    load_wchunk(sb + SM_B, g_WtH[(l + 1) & 3], nbase, c, lid);
            }

            __syncthreads();   // all warps done reading sA

            if (l < 3) {
                // epilogue: sA <- (half)relu(D + bias) for this warp's 32 cols
                const float* bias = (l == 0) ? sB2 : (l == 1) ? sB3 : sB4;
#pragma unroll
                for (int j = 0; j < 4; j++) {
                    const int col = nbase + 8 * j + 2 * t;
                    const float bs0 = bias[col], bs1 = bias[col + 1];
#pragma unroll
                    for (int i = 0; i < 8; i++) {
                        const int row = 16 * i + g;
                        *(__half2*)(sA + (size_t)row * A_STRIDE + col) =
                            __floats2half2_rn(fmaxf(acc[i][j][0] + bs0, 0.f),
                                              fmaxf(acc[i][j][1] + bs1, 0.f));
                        *(__half2*)(sA + (size_t)(row + 8) * A_STRIDE + col) =
                            __floats2half2_rn(fmaxf(acc[i][j][2] + bs0, 0.f),
                                              fmaxf(acc[i][j][3] + bs1, 0.f));
                    }
                }
                __syncthreads();
            } else {
                // ---- Layer 6: out = relu(D + b5) . W6 + b6 ----
                float r0[8], r1[8];
#pragma unroll
                for (int i = 0; i < 8; i++) { r0[i] = 0.f; r1[i] = 0.f; }
#pragma unroll
                for (int j = 0; j < 4; j++) {
                    const int col = nbase + 8 * j + 2 * t;
                    const float w0 = sW6[col], w1 = sW6[col + 1];
                    const float s0 = sB5[col], s1 = sB5[col + 1];
#pragma unroll
                    for (int i = 0; i < 8; i++) {
                        r0[i] = fmaf(fmaxf(acc[i][j][0] + s0, 0.f), w0, r0[i]);
                        r0[i] = fmaf(fmaxf(acc[i][j][1] + s1, 0.f), w1, r0[i]);
                        r1[i] = fmaf(fmaxf(acc[i][j][2] + s0, 0.f), w0, r1[i]);
                        r1[i] = fmaf(fmaxf(acc[i][j][3] + s1, 0.f), w1, r1[i]);
                    }
                }
#pragma unroll
                for (int d = 1; d <= 2; d <<= 1) {
#pragma unroll
                    for (int i = 0; i < 8; i++) {
                        r0[i] += __shfl_xor_sync(0xFFFFFFFFu, r0[i], d);
                        r1[i] += __shfl_xor_sync(0xFFFFFFFFu, r1[i], d);
                    }
                }
                if (t == 0) {
                    float* part = sPart + wid * 128;
#pragma unroll
                    for (int i = 0; i < 8; i++) {
                        part[16 * i + g]     = r0[i];
                        part[16 * i + g + 8] = r1[i];
                    }
                }
                __syncthreads();
                if (tid < TILE_M) {
                    float s = sB6[0];
#pragma unroll
                    for (int w = 0; w < 8; w++) s += sPart[w * 128 + tid];
                    out[row_base + tid] = s;
                }
                __syncthreads();   // sPart/sA safe before next tile
            }
        }
    }
}

// ---------------------------------------------------------------------------
extern "C" void kernel_launch(void* const* d_in, const int* in_sizes, int n_in,
                              void* d_out, int out_size) {
    const float* coords = (const float*)d_in[0];
    const float* W1 = (const float*)d_in[1];
    const float* b1 = (const float*)d_in[2];
    const float* W2 = (const float*)d_in[3];
    const float* b2 = (const float*)d_in[4];
    const float* W3 = (const float*)d_in[5];
    const float* b3 = (const float*)d_in[6];
    const float* W4 = (const float*)d_in[7];
    const float* b4 = (const float*)d_in[8];
    const float* W5 = (const float*)d_in[9];
    const float* b5 = (const float*)d_in[10];
    const float* W6 = (const float*)d_in[11];
    const float* b6 = (const float*)d_in[12];
    float* out = (float*)d_out;

    const int n = in_sizes[0] / 2;      // rows
    const int ntiles = n / TILE_M;      // 4096

    int nsm = 148;
    cudaDeviceGetAttribute(&nsm, cudaDevAttrMultiProcessorCount, 0);
    const int grid = (nsm < ntiles) ? nsm : ntiles;

    transpose_w_kernel<<<dim3(NDIM / 32, KDIM / 32, 4), dim3(32, 8)>>>(W2, W3, W4, W5);

    cudaFuncSetAttribute(mlp_kernel, cudaFuncAttributeMaxDynamicSharedMemorySize, SMEM_TOTAL);
    mlp_kernel<<<grid, THREADS, SMEM_TOTAL>>>(coords, W1, b1, b2, b3, b4, b5,
                                              W6, b6, out, ntiles);
}